// round 12
// baseline (speedup 1.0000x reference)
#include <cuda_runtime.h>
#include <cuda_fp16.h>
#include <math.h>

#define MAXN 40000
#define MAXE 640000
#define D 128
#define H 4
#define C 32
#define NEG_SLOPE 0.2f
#define SCAN_BLK 512

// -------- device scratch (static; no allocation allowed) --------
__device__ __half g_xvh[(size_t)MAXN * D];   // x' @ Wv^T per node (fp16, 10.2 MB)
__device__ float g_ai[MAXN * H];
__device__ float g_aj[MAXN * H];
__device__ float g_WvT[D * D];
__device__ float g_qvec[H * D];
__device__ float g_kvec[H * D];
__device__ float g_xv_edge[8 * D];
__device__ float g_aj_edge[8 * H];
__device__ int   g_deg[MAXN];
__device__ int   g_rowstart[MAXN + 1];
__device__ int   g_cursor[MAXN];
__device__ int   g_adj[MAXE];                // src | (et<<24)
__device__ int   g_bsum[256];
__device__ int   g_boff[256];

// ---- f32x2 helpers (sm_103a packed fp32 FMA) ----
__device__ __forceinline__ unsigned long long pack2(float x, float y) {
    unsigned long long r;
    asm("mov.b64 %0, {%1, %2};" : "=l"(r) : "f"(x), "f"(y));
    return r;
}
__device__ __forceinline__ void unpack2(unsigned long long v, float& x, float& y) {
    asm("mov.b64 {%0, %1}, %2;" : "=f"(x), "=f"(y) : "l"(v));
}
__device__ __forceinline__ void fma2(unsigned long long& acc, unsigned long long a,
                                     unsigned long long b) {
    asm("fma.rn.f32x2 %0, %1, %2, %0;" : "+l"(acc) : "l"(a), "l"(b));
}
__device__ __forceinline__ float4 h4_to_f4(uint2 u) {
    __half2 a = *reinterpret_cast<__half2*>(&u.x);
    __half2 b = *reinterpret_cast<__half2*>(&u.y);
    float2 fa = __half22float2(a);
    float2 fb = __half22float2(b);
    return make_float4(fa.x, fa.y, fb.x, fb.y);
}

// -------- widened precompute: grid = 140 blocks x 128 threads --------
__global__ void precompute_kernel(const float* __restrict__ Wq,
                                  const float* __restrict__ Wk,
                                  const float* __restrict__ Wv,
                                  const float* __restrict__ att_i,
                                  const float* __restrict__ att_j,
                                  const float* __restrict__ edge_emb) {
    int b = blockIdx.x, t = threadIdx.x;
    if (b < 4) {
        int h = b, d = t;
        float q = 0.f, k = 0.f;
        #pragma unroll
        for (int c = 0; c < C; c++) {
            q = fmaf(__ldg(&Wq[(h * C + c) * D + d]), __ldg(&att_i[h * C + c]), q);
            k = fmaf(__ldg(&Wk[(h * C + c) * D + d]), __ldg(&att_j[h * C + c]), k);
        }
        g_qvec[h * D + d] = q;
        g_kvec[h * D + d] = k;
        __shared__ float red[D];
        for (int et = 0; et < 8; et++) {
            red[t] = __ldg(&edge_emb[et * D + t]) * k;
            __syncthreads();
            for (int s = 64; s > 0; s >>= 1) {
                if (t < s) red[t] += red[t + s];
                __syncthreads();
            }
            if (t == 0) g_aj_edge[et * H + h] = red[0];
            __syncthreads();
        }
    } else if (b < 12) {
        int et = b - 4;
        float s = 0.f;
        for (int dd = 0; dd < D; dd++)
            s = fmaf(__ldg(&Wv[t * D + dd]), __ldg(&edge_emb[et * D + dd]), s);
        g_xv_edge[et * D + t] = s;
    } else {
        int i = (b - 12) * 128 + t;
        int d = i >> 7, o = i & 127;
        g_WvT[i] = __ldg(&Wv[o * D + d]);
    }
}

// -------- CSR build --------
__global__ void zero_kernel(int N) {
    int i = blockIdx.x * blockDim.x + threadIdx.x;
    if (i < N) g_deg[i] = 0;
}

// 4 edges per thread, int4 loads (E is divisible by 4; tail guarded anyway)
__global__ void hist_kernel(const int* __restrict__ ei, int E) {
    int q = blockIdx.x * blockDim.x + threadIdx.x;
    int e = q * 4;
    if (e + 3 < E) {
        int4 d4 = __ldg(reinterpret_cast<const int4*>(ei + E + e));
        atomicAdd(&g_deg[d4.x], 1);
        atomicAdd(&g_deg[d4.y], 1);
        atomicAdd(&g_deg[d4.z], 1);
        atomicAdd(&g_deg[d4.w], 1);
    } else {
        for (; e < E; e++) atomicAdd(&g_deg[__ldg(&ei[E + e])], 1);
    }
}

// phase 1: per-block local scan + block sums (full-warp shuffles only)
__global__ void scan1_kernel(int N) {
    __shared__ int ws[SCAN_BLK / 32];
    int t = threadIdx.x, lane = t & 31, wid = t >> 5;
    int idx = blockIdx.x * SCAN_BLK + t;
    int v = (idx < N) ? g_deg[idx] : 0;
    int s = v;
    #pragma unroll
    for (int o = 1; o < 32; o <<= 1) {
        int y = __shfl_up_sync(0xFFFFFFFFu, s, o);
        if (lane >= o) s += y;
    }
    if (lane == 31) ws[wid] = s;
    __syncthreads();
    if (wid == 0) {
        int wv = (lane < SCAN_BLK / 32) ? ws[lane] : 0;
        #pragma unroll
        for (int o = 1; o < SCAN_BLK / 32; o <<= 1) {
            int y = __shfl_up_sync(0xFFFFFFFFu, wv, o);
            if (lane >= o) wv += y;
        }
        if (lane < SCAN_BLK / 32) ws[lane] = wv;
    }
    __syncthreads();
    int base = (wid > 0) ? ws[wid - 1] : 0;
    if (idx < N) g_rowstart[idx] = base + s - v;
    if (t == 0) g_bsum[blockIdx.x] = ws[SCAN_BLK / 32 - 1];
}

// phase 2: scan the (<=256) block sums
__global__ void scan2_kernel(int nb, int N) {
    __shared__ int ws[8];
    int t = threadIdx.x, lane = t & 31, wid = t >> 5;  // 256 threads
    int v = (t < nb) ? g_bsum[t] : 0;
    int s = v;
    #pragma unroll
    for (int o = 1; o < 32; o <<= 1) {
        int y = __shfl_up_sync(0xFFFFFFFFu, s, o);
        if (lane >= o) s += y;
    }
    if (lane == 31) ws[wid] = s;
    __syncthreads();
    int add = 0;
    for (int w = 0; w < wid; w++) add += ws[w];
    s += add;
    if (t < nb) g_boff[t] = s - v;
    if (t == nb - 1) g_rowstart[N] = s;
}

// phase 3: add block offsets, init cursor
__global__ void scan3_kernel(int N) {
    int idx = blockIdx.x * SCAN_BLK + threadIdx.x;
    if (idx < N) {
        int r = g_rowstart[idx] + g_boff[blockIdx.x];
        g_rowstart[idx] = r;
        g_cursor[idx] = r;
    }
}

// 2 edges per thread, int2 loads
__global__ void scatter_kernel(const int* __restrict__ ei,
                               const int* __restrict__ edge_type, int E) {
    int q = blockIdx.x * blockDim.x + threadIdx.x;
    int e = q * 2;
    if (e + 1 < E) {
        int2 s2 = __ldg(reinterpret_cast<const int2*>(ei + e));
        int2 d2 = __ldg(reinterpret_cast<const int2*>(ei + E + e));
        int2 t2 = __ldg(reinterpret_cast<const int2*>(edge_type + e));
        int pos0 = atomicAdd(&g_cursor[d2.x], 1);
        g_adj[pos0] = s2.x | (t2.x << 24);
        int pos1 = atomicAdd(&g_cursor[d2.y], 1);
        g_adj[pos1] = s2.y | (t2.y << 24);
    } else if (e < E) {
        int src = __ldg(&ei[e]);
        int dst = __ldg(&ei[E + e]);
        int et  = __ldg(&edge_type[e]);
        int pos = atomicAdd(&g_cursor[dst], 1);
        g_adj[pos] = src | (et << 24);
    }
}

// -------- per-node: x' = x + emb; xv = x'@Wv^T (f32x2); ai/aj --------
#define MTILE 16
__global__ void node_kernel(const float* __restrict__ x,
                            const int* __restrict__ node_type,
                            const float* __restrict__ node_emb, int N) {
    __shared__ float xs[D * 18];
    int t = threadIdx.x;          // 128
    int base = blockIdx.x * MTILE;
    #pragma unroll
    for (int m = 0; m < MTILE; m++) {
        int n = base + m;
        float val = 0.f;
        if (n < N) {
            int nt = __ldg(&node_type[n]);
            val = __ldg(&x[(size_t)n * D + t]) + __ldg(&node_emb[nt * D + t]);
        }
        xs[t * 18 + m] = val;
    }
    __syncthreads();

    unsigned long long acc2[8];
    #pragma unroll
    for (int i = 0; i < 8; i++) acc2[i] = pack2(0.f, 0.f);

    #pragma unroll 4
    for (int d = 0; d < D; d++) {
        float w = g_WvT[d * D + t];
        unsigned long long ww = pack2(w, w);
        const float2* xr = reinterpret_cast<const float2*>(&xs[d * 18]);
        #pragma unroll
        for (int i = 0; i < 8; i++) {
            float2 xp = xr[i];
            unsigned long long xp2 = *reinterpret_cast<unsigned long long*>(&xp);
            fma2(acc2[i], xp2, ww);
        }
    }
    #pragma unroll
    for (int i = 0; i < 8; i++) {
        float lo, hi;
        unpack2(acc2[i], lo, hi);
        int n0 = base + 2 * i;
        if (n0 < N)     g_xvh[(size_t)n0 * D + t]       = __float2half(lo);
        if (n0 + 1 < N) g_xvh[(size_t)(n0 + 1) * D + t] = __float2half(hi);
    }

    if (t < 64) {
        int m = t >> 2, h = t & 3;
        int n = base + m;
        if (n < N) {
            float ai = 0.f, aj = 0.f;
            for (int d = 0; d < D; d++) {
                float xv = xs[d * 18 + m];
                ai = fmaf(xv, g_qvec[h * D + d], ai);
                aj = fmaf(xv, g_kvec[h * D + d], aj);
            }
            g_ai[n * H + h] = ai;
            g_aj[n * H + h] = aj;
        }
    }
}

// -------- gather: one warp per dst node, 8-wide unrolled for MLP --------
__global__ void gather_kernel(float* __restrict__ out,
                              const float* __restrict__ bias, int N) {
    __shared__ float s_xve[8 * D];
    __shared__ float s_aje[8 * H];
    int tid = threadIdx.x;
    for (int i = tid; i < 8 * D; i += blockDim.x) s_xve[i] = g_xv_edge[i];
    if (tid < 32) s_aje[tid] = g_aj_edge[tid];
    __syncthreads();

    int n = (blockIdx.x * blockDim.x + tid) >> 5;
    int lane = tid & 31;
    if (n >= N) return;
    int h = lane >> 3;

    float ai_h = __ldg(&g_ai[n * H + h]);

    // self-loop (edge type 0)
    float a = ai_h + __ldg(&g_aj[n * H + h]) + s_aje[h];
    a = fmaxf(a, NEG_SLOPE * a);
    float w = __expf(a);
    float denom = w;
    uint2 hv = __ldg(reinterpret_cast<const uint2*>(g_xvh + (size_t)n * D) + lane);
    float4 v = h4_to_f4(hv);
    float4 ev = *reinterpret_cast<const float4*>(&s_xve[lane * 4]);
    float4 acc;
    acc.x = w * (v.x + ev.x);
    acc.y = w * (v.y + ev.y);
    acc.z = w * (v.z + ev.z);
    acc.w = w * (v.w + ev.w);

    int row0 = __ldg(&g_rowstart[n]);
    int row1 = __ldg(&g_rowstart[n + 1]);
    for (int bs = row0; bs < row1; bs += 32) {
        int rem = row1 - bs;
        int cnt = min(rem, 32);
        int p = (lane < cnt) ? __ldg(&g_adj[bs + lane]) : 0;
        int j = 0;
        // 8-wide: issue all gathers up front for MLP
        for (; j + 7 < cnt; j += 8) {
            int   sv[8], et[8];
            float ajv[8];
            uint2 hvv[8];
            #pragma unroll
            for (int i = 0; i < 8; i++) {
                int pp = __shfl_sync(0xFFFFFFFFu, p, j + i);
                sv[i] = pp & 0xFFFFFF;
                et[i] = pp >> 24;
            }
            #pragma unroll
            for (int i = 0; i < 8; i++)
                ajv[i] = __ldg(&g_aj[sv[i] * H + h]);
            #pragma unroll
            for (int i = 0; i < 8; i++)
                hvv[i] = __ldg(reinterpret_cast<const uint2*>(g_xvh + (size_t)sv[i] * D) + lane);
            #pragma unroll
            for (int i = 0; i < 8; i++) {
                float ae = ai_h + ajv[i] + s_aje[et[i] * H + h];
                ae = fmaxf(ae, NEG_SLOPE * ae);
                float we = __expf(ae);
                denom += we;
                float4 ve = h4_to_f4(hvv[i]);
                const float4 ee = *reinterpret_cast<const float4*>(&s_xve[et[i] * D + lane * 4]);
                acc.x = fmaf(we, ve.x + ee.x, acc.x);
                acc.y = fmaf(we, ve.y + ee.y, acc.y);
                acc.z = fmaf(we, ve.z + ee.z, acc.z);
                acc.w = fmaf(we, ve.w + ee.w, acc.w);
            }
        }
        for (; j < cnt; j++) {
            int p0 = __shfl_sync(0xFFFFFFFFu, p, j);
            int s0 = p0 & 0xFFFFFF, e0 = p0 >> 24;
            float aj0 = __ldg(&g_aj[s0 * H + h]);
            uint2 h0 = __ldg(reinterpret_cast<const uint2*>(g_xvh + (size_t)s0 * D) + lane);
            float a0 = ai_h + aj0 + s_aje[e0 * H + h];
            a0 = fmaxf(a0, NEG_SLOPE * a0);
            float w0 = __expf(a0);
            denom += w0;
            float4 v0 = h4_to_f4(h0);
            const float4 ee0 = *reinterpret_cast<const float4*>(&s_xve[e0 * D + lane * 4]);
            acc.x = fmaf(w0, v0.x + ee0.x, acc.x);
            acc.y = fmaf(w0, v0.y + ee0.y, acc.y);
            acc.z = fmaf(w0, v0.z + ee0.z, acc.z);
            acc.w = fmaf(w0, v0.w + ee0.w, acc.w);
        }
    }

    float inv = 1.f / (denom + 1e-16f);
    float4 b4 = __ldg(reinterpret_cast<const float4*>(bias) + lane);
    float4 r;
    r.x = fmaf(acc.x, inv, b4.x);
    r.y = fmaf(acc.y, inv, b4.y);
    r.z = fmaf(acc.z, inv, b4.z);
    r.w = fmaf(acc.w, inv, b4.w);
    reinterpret_cast<float4*>(out + (size_t)n * D)[lane] = r;
}

extern "C" void kernel_launch(void* const* d_in, const int* in_sizes, int n_in,
                              void* d_out, int out_size) {
    const float* x         = (const float*)d_in[0];
    const int*   ei        = (const int*)  d_in[1];
    const int*   node_type = (const int*)d_in[2];
    const int*   edge_type = (const int*)d_in[3];
    const float* Wq        = (const float*)d_in[4];
    const float* Wk        = (const float*)d_in[5];
    const float* Wv        = (const float*)d_in[6];
    const float* att_i     = (const float*)d_in[7];
    const float* att_j     = (const float*)d_in[8];
    const float* bias      = (const float*)d_in[9];
    const float* node_emb  = (const float*)d_in[10];
    const float* edge_emb  = (const float*)d_in[11];
    float* out = (float*)d_out;

    int N = in_sizes[2];
    int E = in_sizes[3];
    int nb = (N + SCAN_BLK - 1) / SCAN_BLK;

    // fork capture: branch B (precompute -> node GEMM) parallel to CSR build
    cudaStream_t s2;
    cudaEvent_t evFork, evJoin;
    cudaStreamCreateWithFlags(&s2, cudaStreamNonBlocking);
    cudaEventCreateWithFlags(&evFork, cudaEventDisableTiming);
    cudaEventCreateWithFlags(&evJoin, cudaEventDisableTiming);

    cudaEventRecord(evFork, 0);
    cudaStreamWaitEvent(s2, evFork, 0);
    precompute_kernel<<<140, 128, 0, s2>>>(Wq, Wk, Wv, att_i, att_j, edge_emb);
    node_kernel<<<(N + MTILE - 1) / MTILE, 128, 0, s2>>>(x, node_type, node_emb, N);
    cudaEventRecord(evJoin, s2);

    // branch A: CSR build on capture stream
    zero_kernel<<<(N + 255) / 256, 256>>>(N);
    hist_kernel<<<(E / 4 + 255) / 256, 256>>>(ei, E);
    scan1_kernel<<<nb, SCAN_BLK>>>(N);
    scan2_kernel<<<1, 256>>>(nb, N);
    scan3_kernel<<<nb, SCAN_BLK>>>(N);
    scatter_kernel<<<(E / 2 + 255) / 256, 256>>>(ei, edge_type, E);

    // join, then gather
    cudaStreamWaitEvent(0, evJoin, 0);
    gather_kernel<<<(N * 32 + 255) / 256, 256>>>(out, bias, N);
}

// round 14
// speedup vs baseline: 1.0331x; 1.0331x over previous
#include <cuda_runtime.h>
#include <cuda_fp16.h>
#include <math.h>

#define MAXN 40000
#define MAXE 640000
#define D 128
#define H 4
#define C 32
#define NEG_SLOPE 0.2f
#define SCAN_BLK 512

// -------- device scratch (static; no allocation allowed) --------
__device__ __half g_xvh[(size_t)MAXN * D];   // x' @ Wv^T per node (fp16, 10.2 MB)
__device__ float g_ai[MAXN * H];
__device__ float g_aj[MAXN * H];
__device__ float g_WvT[D * D];
__device__ float g_qvec[H * D];
__device__ float g_kvec[H * D];
__device__ float g_xv_edge[8 * D];
__device__ float g_aj_edge[8 * H];
__device__ int   g_deg[MAXN];
__device__ int   g_rowstart[MAXN + 1];
__device__ int   g_cursor[MAXN];
__device__ int   g_adj[MAXE];                // src | (et<<24)
__device__ int   g_bsum[256];
__device__ int   g_boff[256];

// ---- f32x2 helpers (sm_103a packed fp32 FMA) ----
__device__ __forceinline__ unsigned long long pack2(float x, float y) {
    unsigned long long r;
    asm("mov.b64 %0, {%1, %2};" : "=l"(r) : "f"(x), "f"(y));
    return r;
}
__device__ __forceinline__ void unpack2(unsigned long long v, float& x, float& y) {
    asm("mov.b64 {%0, %1}, %2;" : "=f"(x), "=f"(y) : "l"(v));
}
__device__ __forceinline__ void fma2(unsigned long long& acc, unsigned long long a,
                                     unsigned long long b) {
    asm("fma.rn.f32x2 %0, %1, %2, %0;" : "+l"(acc) : "l"(a), "l"(b));
}
__device__ __forceinline__ float4 h4_to_f4(uint2 u) {
    __half2 a = *reinterpret_cast<__half2*>(&u.x);
    __half2 b = *reinterpret_cast<__half2*>(&u.y);
    float2 fa = __half22float2(a);
    float2 fb = __half22float2(b);
    return make_float4(fa.x, fa.y, fb.x, fb.y);
}

// -------- widened precompute: grid = 140 blocks x 128 threads --------
__global__ void precompute_kernel(const float* __restrict__ Wq,
                                  const float* __restrict__ Wk,
                                  const float* __restrict__ Wv,
                                  const float* __restrict__ att_i,
                                  const float* __restrict__ att_j,
                                  const float* __restrict__ edge_emb) {
    int b = blockIdx.x, t = threadIdx.x;
    if (b < 4) {
        int h = b, d = t;
        float q = 0.f, k = 0.f;
        #pragma unroll
        for (int c = 0; c < C; c++) {
            q = fmaf(__ldg(&Wq[(h * C + c) * D + d]), __ldg(&att_i[h * C + c]), q);
            k = fmaf(__ldg(&Wk[(h * C + c) * D + d]), __ldg(&att_j[h * C + c]), k);
        }
        g_qvec[h * D + d] = q;
        g_kvec[h * D + d] = k;
        __shared__ float red[D];
        for (int et = 0; et < 8; et++) {
            red[t] = __ldg(&edge_emb[et * D + t]) * k;
            __syncthreads();
            for (int s = 64; s > 0; s >>= 1) {
                if (t < s) red[t] += red[t + s];
                __syncthreads();
            }
            if (t == 0) g_aj_edge[et * H + h] = red[0];
            __syncthreads();
        }
    } else if (b < 12) {
        int et = b - 4;
        float s = 0.f;
        for (int dd = 0; dd < D; dd++)
            s = fmaf(__ldg(&Wv[t * D + dd]), __ldg(&edge_emb[et * D + dd]), s);
        g_xv_edge[et * D + t] = s;
    } else {
        int i = (b - 12) * 128 + t;
        int d = i >> 7, o = i & 127;
        g_WvT[i] = __ldg(&Wv[o * D + d]);
    }
}

// -------- CSR build --------
__global__ void zero_kernel(int N) {
    int i = blockIdx.x * blockDim.x + threadIdx.x;
    if (i < N) g_deg[i] = 0;
}

__global__ void hist_kernel(const int* __restrict__ ei, int E) {
    int e = blockIdx.x * blockDim.x + threadIdx.x;
    if (e < E) atomicAdd(&g_deg[__ldg(&ei[E + e])], 1);
}

// phase 1: per-block local scan + block sums (full-warp shuffles only)
__global__ void scan1_kernel(int N) {
    __shared__ int ws[SCAN_BLK / 32];
    int t = threadIdx.x, lane = t & 31, wid = t >> 5;
    int idx = blockIdx.x * SCAN_BLK + t;
    int v = (idx < N) ? g_deg[idx] : 0;
    int s = v;
    #pragma unroll
    for (int o = 1; o < 32; o <<= 1) {
        int y = __shfl_up_sync(0xFFFFFFFFu, s, o);
        if (lane >= o) s += y;
    }
    if (lane == 31) ws[wid] = s;
    __syncthreads();
    if (wid == 0) {
        int wv = (lane < SCAN_BLK / 32) ? ws[lane] : 0;
        #pragma unroll
        for (int o = 1; o < SCAN_BLK / 32; o <<= 1) {
            int y = __shfl_up_sync(0xFFFFFFFFu, wv, o);
            if (lane >= o) wv += y;
        }
        if (lane < SCAN_BLK / 32) ws[lane] = wv;
    }
    __syncthreads();
    int base = (wid > 0) ? ws[wid - 1] : 0;
    if (idx < N) g_rowstart[idx] = base + s - v;
    if (t == 0) g_bsum[blockIdx.x] = ws[SCAN_BLK / 32 - 1];
}

// phase 2: scan the (<=256) block sums
__global__ void scan2_kernel(int nb, int N) {
    __shared__ int ws[8];
    int t = threadIdx.x, lane = t & 31, wid = t >> 5;  // 256 threads
    int v = (t < nb) ? g_bsum[t] : 0;
    int s = v;
    #pragma unroll
    for (int o = 1; o < 32; o <<= 1) {
        int y = __shfl_up_sync(0xFFFFFFFFu, s, o);
        if (lane >= o) s += y;
    }
    if (lane == 31) ws[wid] = s;
    __syncthreads();
    int add = 0;
    for (int w = 0; w < wid; w++) add += ws[w];
    s += add;
    if (t < nb) g_boff[t] = s - v;
    if (t == nb - 1) g_rowstart[N] = s;
}

// phase 3: add block offsets, init cursor
__global__ void scan3_kernel(int N) {
    int idx = blockIdx.x * SCAN_BLK + threadIdx.x;
    if (idx < N) {
        int r = g_rowstart[idx] + g_boff[blockIdx.x];
        g_rowstart[idx] = r;
        g_cursor[idx] = r;
    }
}

__global__ void scatter_kernel(const int* __restrict__ ei,
                               const int* __restrict__ edge_type, int E) {
    int e = blockIdx.x * blockDim.x + threadIdx.x;
    if (e < E) {
        int src = __ldg(&ei[e]);
        int dst = __ldg(&ei[E + e]);
        int et  = __ldg(&edge_type[e]);
        int pos = atomicAdd(&g_cursor[dst], 1);
        g_adj[pos] = src | (et << 24);
    }
}

// -------- per-node: x' = x + emb; xv = x'@Wv^T (f32x2); ai/aj --------
#define MTILE 16
__global__ void node_kernel(const float* __restrict__ x,
                            const int* __restrict__ node_type,
                            const float* __restrict__ node_emb, int N) {
    __shared__ float xs[D * 18];
    int t = threadIdx.x;          // 128
    int base = blockIdx.x * MTILE;
    #pragma unroll
    for (int m = 0; m < MTILE; m++) {
        int n = base + m;
        float val = 0.f;
        if (n < N) {
            int nt = __ldg(&node_type[n]);
            val = __ldg(&x[(size_t)n * D + t]) + __ldg(&node_emb[nt * D + t]);
        }
        xs[t * 18 + m] = val;
    }
    __syncthreads();

    unsigned long long acc2[8];
    #pragma unroll
    for (int i = 0; i < 8; i++) acc2[i] = pack2(0.f, 0.f);

    #pragma unroll 4
    for (int d = 0; d < D; d++) {
        float w = g_WvT[d * D + t];
        unsigned long long ww = pack2(w, w);
        const float2* xr = reinterpret_cast<const float2*>(&xs[d * 18]);
        #pragma unroll
        for (int i = 0; i < 8; i++) {
            float2 xp = xr[i];
            unsigned long long xp2 = *reinterpret_cast<unsigned long long*>(&xp);
            fma2(acc2[i], xp2, ww);
        }
    }
    #pragma unroll
    for (int i = 0; i < 8; i++) {
        float lo, hi;
        unpack2(acc2[i], lo, hi);
        int n0 = base + 2 * i;
        if (n0 < N)     g_xvh[(size_t)n0 * D + t]       = __float2half(lo);
        if (n0 + 1 < N) g_xvh[(size_t)(n0 + 1) * D + t] = __float2half(hi);
    }

    if (t < 64) {
        int m = t >> 2, h = t & 3;
        int n = base + m;
        if (n < N) {
            float ai = 0.f, aj = 0.f;
            for (int d = 0; d < D; d++) {
                float xv = xs[d * 18 + m];
                ai = fmaf(xv, g_qvec[h * D + d], ai);
                aj = fmaf(xv, g_kvec[h * D + d], aj);
            }
            g_ai[n * H + h] = ai;
            g_aj[n * H + h] = aj;
        }
    }
}

// -------- gather: one warp per dst node, 4-wide, edge-type weight-sum trick --------
// acc accumulates only w*v[src]; the w*ee[et] part is folded via per-lane wsum
// (lane l owns the (h = l>>3, et = l&7) combo) and applied in an epilogue.
__global__ void gather_kernel(float* __restrict__ out,
                              const float* __restrict__ bias, int N) {
    __shared__ float s_xve[8 * D];
    __shared__ float s_aje[8 * H];
    int tid = threadIdx.x;
    for (int i = tid; i < 8 * D; i += blockDim.x) s_xve[i] = g_xv_edge[i];
    if (tid < 32) s_aje[tid] = g_aj_edge[tid];
    __syncthreads();

    int n = (blockIdx.x * blockDim.x + tid) >> 5;
    int lane = tid & 31;
    if (n >= N) return;
    int h = lane >> 3;
    int my_et = lane & 7;

    float ai_h = __ldg(&g_ai[n * H + h]);

    // self-loop (edge type 0)
    float a = ai_h + __ldg(&g_aj[n * H + h]) + s_aje[h];
    a = fmaxf(a, NEG_SLOPE * a);
    float w = __expf(a);
    float denom = w;
    float wsum = (my_et == 0) ? w : 0.f;   // self-loop et = 0
    uint2 hv = __ldg(reinterpret_cast<const uint2*>(g_xvh + (size_t)n * D) + lane);
    float4 v = h4_to_f4(hv);
    float4 acc;
    acc.x = w * v.x;
    acc.y = w * v.y;
    acc.z = w * v.z;
    acc.w = w * v.w;

    int row0 = __ldg(&g_rowstart[n]);
    int row1 = __ldg(&g_rowstart[n + 1]);
    for (int bs = row0; bs < row1; bs += 32) {
        int rem = row1 - bs;
        int cnt = min(rem, 32);
        int p = (lane < cnt) ? __ldg(&g_adj[bs + lane]) : 0;
        int j = 0;
        for (; j + 3 < cnt; j += 4) {
            int p0 = __shfl_sync(0xFFFFFFFFu, p, j);
            int p1 = __shfl_sync(0xFFFFFFFFu, p, j + 1);
            int p2 = __shfl_sync(0xFFFFFFFFu, p, j + 2);
            int p3 = __shfl_sync(0xFFFFFFFFu, p, j + 3);
            int s0 = p0 & 0xFFFFFF, e0 = p0 >> 24;
            int s1 = p1 & 0xFFFFFF, e1 = p1 >> 24;
            int s2 = p2 & 0xFFFFFF, e2 = p2 >> 24;
            int s3 = p3 & 0xFFFFFF, e3 = p3 >> 24;
            float aj0 = __ldg(&g_aj[s0 * H + h]);
            float aj1 = __ldg(&g_aj[s1 * H + h]);
            float aj2 = __ldg(&g_aj[s2 * H + h]);
            float aj3 = __ldg(&g_aj[s3 * H + h]);
            uint2 h0 = __ldg(reinterpret_cast<const uint2*>(g_xvh + (size_t)s0 * D) + lane);
            uint2 h1 = __ldg(reinterpret_cast<const uint2*>(g_xvh + (size_t)s1 * D) + lane);
            uint2 h2 = __ldg(reinterpret_cast<const uint2*>(g_xvh + (size_t)s2 * D) + lane);
            uint2 h3 = __ldg(reinterpret_cast<const uint2*>(g_xvh + (size_t)s3 * D) + lane);
            float a0 = ai_h + aj0 + s_aje[e0 * H + h];
            float a1 = ai_h + aj1 + s_aje[e1 * H + h];
            float a2 = ai_h + aj2 + s_aje[e2 * H + h];
            float a3 = ai_h + aj3 + s_aje[e3 * H + h];
            a0 = fmaxf(a0, NEG_SLOPE * a0);
            a1 = fmaxf(a1, NEG_SLOPE * a1);
            a2 = fmaxf(a2, NEG_SLOPE * a2);
            a3 = fmaxf(a3, NEG_SLOPE * a3);
            float w0 = __expf(a0), w1 = __expf(a1);
            float w2 = __expf(a2), w3 = __expf(a3);
            denom += w0; denom += w1; denom += w2; denom += w3;
            if (my_et == e0) wsum += w0;
            if (my_et == e1) wsum += w1;
            if (my_et == e2) wsum += w2;
            if (my_et == e3) wsum += w3;
            float4 v0 = h4_to_f4(h0);
            float4 v1 = h4_to_f4(h1);
            float4 v2 = h4_to_f4(h2);
            float4 v3 = h4_to_f4(h3);
            acc.x = fmaf(w0, v0.x, acc.x);
            acc.y = fmaf(w0, v0.y, acc.y);
            acc.z = fmaf(w0, v0.z, acc.z);
            acc.w = fmaf(w0, v0.w, acc.w);
            acc.x = fmaf(w1, v1.x, acc.x);
            acc.y = fmaf(w1, v1.y, acc.y);
            acc.z = fmaf(w1, v1.z, acc.z);
            acc.w = fmaf(w1, v1.w, acc.w);
            acc.x = fmaf(w2, v2.x, acc.x);
            acc.y = fmaf(w2, v2.y, acc.y);
            acc.z = fmaf(w2, v2.z, acc.z);
            acc.w = fmaf(w2, v2.w, acc.w);
            acc.x = fmaf(w3, v3.x, acc.x);
            acc.y = fmaf(w3, v3.y, acc.y);
            acc.z = fmaf(w3, v3.z, acc.z);
            acc.w = fmaf(w3, v3.w, acc.w);
        }
        for (; j < cnt; j++) {
            int p0 = __shfl_sync(0xFFFFFFFFu, p, j);
            int s0 = p0 & 0xFFFFFF, e0 = p0 >> 24;
            float aj0 = __ldg(&g_aj[s0 * H + h]);
            uint2 h0 = __ldg(reinterpret_cast<const uint2*>(g_xvh + (size_t)s0 * D) + lane);
            float a0 = ai_h + aj0 + s_aje[e0 * H + h];
            a0 = fmaxf(a0, NEG_SLOPE * a0);
            float w0 = __expf(a0);
            denom += w0;
            if (my_et == e0) wsum += w0;
            float4 v0 = h4_to_f4(h0);
            acc.x = fmaf(w0, v0.x, acc.x);
            acc.y = fmaf(w0, v0.y, acc.y);
            acc.z = fmaf(w0, v0.z, acc.z);
            acc.w = fmaf(w0, v0.w, acc.w);
        }
    }

    // epilogue: apply edge-type embedding contributions.
    // lane (h*8 + et) holds wsum for (h, et); my h's group base is lane&24.
    #pragma unroll
    for (int et = 0; et < 8; et++) {
        float wet = __shfl_sync(0xFFFFFFFFu, wsum, (lane & 24) | et);
        const float4 ee = *reinterpret_cast<const float4*>(&s_xve[et * D + lane * 4]);
        acc.x = fmaf(wet, ee.x, acc.x);
        acc.y = fmaf(wet, ee.y, acc.y);
        acc.z = fmaf(wet, ee.z, acc.z);
        acc.w = fmaf(wet, ee.w, acc.w);
    }

    float inv = 1.f / (denom + 1e-16f);
    float4 b4 = __ldg(reinterpret_cast<const float4*>(bias) + lane);
    float4 r;
    r.x = fmaf(acc.x, inv, b4.x);
    r.y = fmaf(acc.y, inv, b4.y);
    r.z = fmaf(acc.z, inv, b4.z);
    r.w = fmaf(acc.w, inv, b4.w);
    reinterpret_cast<float4*>(out + (size_t)n * D)[lane] = r;
}

extern "C" void kernel_launch(void* const* d_in, const int* in_sizes, int n_in,
                              void* d_out, int out_size) {
    const float* x         = (const float*)d_in[0];
    const int*   ei        = (const int*)  d_in[1];
    const int*   node_type = (const int*)d_in[2];
    const int*   edge_type = (const int*)d_in[3];
    const float* Wq        = (const float*)d_in[4];
    const float* Wk        = (const float*)d_in[5];
    const float* Wv        = (const float*)d_in[6];
    const float* att_i     = (const float*)d_in[7];
    const float* att_j     = (const float*)d_in[8];
    const float* bias      = (const float*)d_in[9];
    const float* node_emb  = (const float*)d_in[10];
    const float* edge_emb  = (const float*)d_in[11];
    float* out = (float*)d_out;

    int N = in_sizes[2];
    int E = in_sizes[3];
    int nb = (N + SCAN_BLK - 1) / SCAN_BLK;

    // fork capture: branch B (precompute -> node GEMM) parallel to CSR build
    cudaStream_t s2;
    cudaEvent_t evFork, evJoin;
    cudaStreamCreateWithFlags(&s2, cudaStreamNonBlocking);
    cudaEventCreateWithFlags(&evFork, cudaEventDisableTiming);
    cudaEventCreateWithFlags(&evJoin, cudaEventDisableTiming);

    cudaEventRecord(evFork, 0);
    cudaStreamWaitEvent(s2, evFork, 0);
    precompute_kernel<<<140, 128, 0, s2>>>(Wq, Wk, Wv, att_i, att_j, edge_emb);
    node_kernel<<<(N + MTILE - 1) / MTILE, 128, 0, s2>>>(x, node_type, node_emb, N);
    cudaEventRecord(evJoin, s2);

    // branch A: CSR build on capture stream
    zero_kernel<<<(N + 255) / 256, 256>>>(N);
    hist_kernel<<<(E + 255) / 256, 256>>>(ei, E);
    scan1_kernel<<<nb, SCAN_BLK>>>(N);
    scan2_kernel<<<1, 256>>>(nb, N);
    scan3_kernel<<<nb, SCAN_BLK>>>(N);
    scatter_kernel<<<(E + 255) / 256, 256>>>(ei, edge_type, E);

    // join, then gather
    cudaStreamWaitEvent(0, evJoin, 0);
    gather_kernel<<<(N * 32 + 255) / 256, 256>>>(out, bias, N);
}

// round 16
// speedup vs baseline: 1.0465x; 1.0130x over previous
#include <cuda_runtime.h>
#include <cuda_fp16.h>
#include <math.h>

#define MAXN 40000
#define MAXE 640000
#define D 128
#define H 4
#define C 32
#define NEG_SLOPE 0.2f
#define SCAN_BLK 512

// -------- device scratch (static; no allocation allowed) --------
__device__ __half g_xvh[(size_t)MAXN * D];   // x' @ Wv^T per node (fp16, 10.2 MB)
__device__ float g_ai[MAXN * H];
__device__ float g_aj[MAXN * H];
__device__ float g_WvT[D * D];
__device__ float g_qvec[H * D];
__device__ float g_kvec[H * D];
__device__ float g_xv_edge[8 * D];
__device__ float g_aj_edge[8 * H];
__device__ int   g_deg[MAXN];
__device__ int   g_rowstart[MAXN + 1];
__device__ int   g_cursor[MAXN];
__device__ int   g_adj[MAXE];                // src | (et<<24)
__device__ int   g_bsum[256];

// ---- f32x2 helpers (sm_103a packed fp32 FMA) ----
__device__ __forceinline__ unsigned long long pack2(float x, float y) {
    unsigned long long r;
    asm("mov.b64 %0, {%1, %2};" : "=l"(r) : "f"(x), "f"(y));
    return r;
}
__device__ __forceinline__ void unpack2(unsigned long long v, float& x, float& y) {
    asm("mov.b64 {%0, %1}, %2;" : "=f"(x), "=f"(y) : "l"(v));
}
__device__ __forceinline__ void fma2(unsigned long long& acc, unsigned long long a,
                                     unsigned long long b) {
    asm("fma.rn.f32x2 %0, %1, %2, %0;" : "+l"(acc) : "l"(a), "l"(b));
}
__device__ __forceinline__ float4 h4_to_f4(uint2 u) {
    __half2 a = *reinterpret_cast<__half2*>(&u.x);
    __half2 b = *reinterpret_cast<__half2*>(&u.y);
    float2 fa = __half22float2(a);
    float2 fb = __half22float2(b);
    return make_float4(fa.x, fa.y, fb.x, fb.y);
}

// -------- fused precompute + deg-zero: blocks 0-139 precompute, 140+ zero --------
__global__ void precompute_kernel(const float* __restrict__ Wq,
                                  const float* __restrict__ Wk,
                                  const float* __restrict__ Wv,
                                  const float* __restrict__ att_i,
                                  const float* __restrict__ att_j,
                                  const float* __restrict__ edge_emb, int N) {
    int b = blockIdx.x, t = threadIdx.x;
    if (b < 4) {
        int h = b, d = t;
        float q = 0.f, k = 0.f;
        #pragma unroll
        for (int c = 0; c < C; c++) {
            q = fmaf(__ldg(&Wq[(h * C + c) * D + d]), __ldg(&att_i[h * C + c]), q);
            k = fmaf(__ldg(&Wk[(h * C + c) * D + d]), __ldg(&att_j[h * C + c]), k);
        }
        g_qvec[h * D + d] = q;
        g_kvec[h * D + d] = k;
        __shared__ float red[D];
        for (int et = 0; et < 8; et++) {
            red[t] = __ldg(&edge_emb[et * D + t]) * k;
            __syncthreads();
            for (int s = 64; s > 0; s >>= 1) {
                if (t < s) red[t] += red[t + s];
                __syncthreads();
            }
            if (t == 0) g_aj_edge[et * H + h] = red[0];
            __syncthreads();
        }
    } else if (b < 12) {
        int et = b - 4;
        float s = 0.f;
        for (int dd = 0; dd < D; dd++)
            s = fmaf(__ldg(&Wv[t * D + dd]), __ldg(&edge_emb[et * D + dd]), s);
        g_xv_edge[et * D + t] = s;
    } else if (b < 140) {
        int i = (b - 12) * 128 + t;
        int d = i >> 7, o = i & 127;
        g_WvT[i] = __ldg(&Wv[o * D + d]);
    } else {
        // zero g_deg: blocks 140.. cover N ints
        int i = (b - 140) * 128 + t;
        if (i < N) g_deg[i] = 0;
    }
}

__global__ void hist_kernel(const int* __restrict__ ei, int E) {
    int e = blockIdx.x * blockDim.x + threadIdx.x;
    if (e < E) atomicAdd(&g_deg[__ldg(&ei[E + e])], 1);
}

// phase 1: per-block local scan + block sums (full-warp shuffles only)
__global__ void scan1_kernel(int N) {
    __shared__ int ws[SCAN_BLK / 32];
    int t = threadIdx.x, lane = t & 31, wid = t >> 5;
    int idx = blockIdx.x * SCAN_BLK + t;
    int v = (idx < N) ? g_deg[idx] : 0;
    int s = v;
    #pragma unroll
    for (int o = 1; o < 32; o <<= 1) {
        int y = __shfl_up_sync(0xFFFFFFFFu, s, o);
        if (lane >= o) s += y;
    }
    if (lane == 31) ws[wid] = s;
    __syncthreads();
    if (wid == 0) {
        int wv = (lane < SCAN_BLK / 32) ? ws[lane] : 0;
        #pragma unroll
        for (int o = 1; o < SCAN_BLK / 32; o <<= 1) {
            int y = __shfl_up_sync(0xFFFFFFFFu, wv, o);
            if (lane >= o) wv += y;
        }
        if (lane < SCAN_BLK / 32) ws[lane] = wv;
    }
    __syncthreads();
    int base = (wid > 0) ? ws[wid - 1] : 0;
    if (idx < N) g_rowstart[idx] = base + s - v;
    if (t == 0) g_bsum[blockIdx.x] = ws[SCAN_BLK / 32 - 1];
}

// phase 2 (fused scan2+scan3): each block reduces its own prefix of bsum,
// then adds it to its local exclusive scans and inits the cursor.
__global__ void scan3_kernel(int N) {
    __shared__ int red[SCAN_BLK / 32];
    int t = threadIdx.x, lane = t & 31, wid = t >> 5;
    int b = blockIdx.x;
    // sum of g_bsum[0..b-1] via block reduction (b <= 255 < SCAN_BLK)
    int v = (t < b) ? g_bsum[t] : 0;
    #pragma unroll
    for (int o = 16; o > 0; o >>= 1)
        v += __shfl_down_sync(0xFFFFFFFFu, v, o);
    if (lane == 0) red[wid] = v;
    __syncthreads();
    if (wid == 0) {
        int s = (lane < SCAN_BLK / 32) ? red[lane] : 0;
        #pragma unroll
        for (int o = 8; o > 0; o >>= 1)
            s += __shfl_down_sync(0xFFFFFFFFu, s, o);
        if (lane == 0) red[0] = s;
    }
    __syncthreads();
    int boff = red[0];

    int idx = b * SCAN_BLK + t;
    if (idx < N) {
        int r = g_rowstart[idx] + boff;
        g_rowstart[idx] = r;
        g_cursor[idx] = r;
    }
    if (b == gridDim.x - 1 && t == 0)
        g_rowstart[N] = boff + g_bsum[b];
}

__global__ void scatter_kernel(const int* __restrict__ ei,
                               const int* __restrict__ edge_type, int E) {
    int e = blockIdx.x * blockDim.x + threadIdx.x;
    if (e < E) {
        int src = __ldg(&ei[e]);
        int dst = __ldg(&ei[E + e]);
        int et  = __ldg(&edge_type[e]);
        int pos = atomicAdd(&g_cursor[dst], 1);
        g_adj[pos] = src | (et << 24);
    }
}

// -------- per-node: x' = x + emb; xv = x'@Wv^T (f32x2); ai/aj --------
#define MTILE 16
__global__ void node_kernel(const float* __restrict__ x,
                            const int* __restrict__ node_type,
                            const float* __restrict__ node_emb, int N) {
    __shared__ float xs[D * 18];
    int t = threadIdx.x;          // 128
    int base = blockIdx.x * MTILE;
    #pragma unroll
    for (int m = 0; m < MTILE; m++) {
        int n = base + m;
        float val = 0.f;
        if (n < N) {
            int nt = __ldg(&node_type[n]);
            val = __ldg(&x[(size_t)n * D + t]) + __ldg(&node_emb[nt * D + t]);
        }
        xs[t * 18 + m] = val;
    }
    __syncthreads();

    unsigned long long acc2[8];
    #pragma unroll
    for (int i = 0; i < 8; i++) acc2[i] = pack2(0.f, 0.f);

    #pragma unroll 4
    for (int d = 0; d < D; d++) {
        float w = g_WvT[d * D + t];
        unsigned long long ww = pack2(w, w);
        const float2* xr = reinterpret_cast<const float2*>(&xs[d * 18]);
        #pragma unroll
        for (int i = 0; i < 8; i++) {
            float2 xp = xr[i];
            unsigned long long xp2 = *reinterpret_cast<unsigned long long*>(&xp);
            fma2(acc2[i], xp2, ww);
        }
    }
    #pragma unroll
    for (int i = 0; i < 8; i++) {
        float lo, hi;
        unpack2(acc2[i], lo, hi);
        int n0 = base + 2 * i;
        if (n0 < N)     g_xvh[(size_t)n0 * D + t]       = __float2half(lo);
        if (n0 + 1 < N) g_xvh[(size_t)(n0 + 1) * D + t] = __float2half(hi);
    }

    if (t < 64) {
        int m = t >> 2, h = t & 3;
        int n = base + m;
        if (n < N) {
            float ai = 0.f, aj = 0.f;
            for (int d = 0; d < D; d++) {
                float xv = xs[d * 18 + m];
                ai = fmaf(xv, g_qvec[h * D + d], ai);
                aj = fmaf(xv, g_kvec[h * D + d], aj);
            }
            g_ai[n * H + h] = ai;
            g_aj[n * H + h] = aj;
        }
    }
}

// -------- gather: one warp per dst node, 4-wide, edge-type weight-sum trick --------
__global__ void gather_kernel(float* __restrict__ out,
                              const float* __restrict__ bias, int N) {
    __shared__ float s_xve[8 * D];
    __shared__ float s_aje[8 * H];
    int tid = threadIdx.x;
    for (int i = tid; i < 8 * D; i += blockDim.x) s_xve[i] = g_xv_edge[i];
    if (tid < 32) s_aje[tid] = g_aj_edge[tid];
    __syncthreads();

    int n = (blockIdx.x * blockDim.x + tid) >> 5;
    int lane = tid & 31;
    if (n >= N) return;
    int h = lane >> 3;
    int my_et = lane & 7;

    float ai_h = __ldg(&g_ai[n * H + h]);

    // self-loop (edge type 0)
    float a = ai_h + __ldg(&g_aj[n * H + h]) + s_aje[h];
    a = fmaxf(a, NEG_SLOPE * a);
    float w = __expf(a);
    float denom = w;
    float wsum = (my_et == 0) ? w : 0.f;   // self-loop et = 0
    uint2 hv = __ldg(reinterpret_cast<const uint2*>(g_xvh + (size_t)n * D) + lane);
    float4 v = h4_to_f4(hv);
    float4 acc;
    acc.x = w * v.x;
    acc.y = w * v.y;
    acc.z = w * v.z;
    acc.w = w * v.w;

    int row0 = __ldg(&g_rowstart[n]);
    int row1 = __ldg(&g_rowstart[n + 1]);
    for (int bs = row0; bs < row1; bs += 32) {
        int rem = row1 - bs;
        int cnt = min(rem, 32);
        int p = (lane < cnt) ? __ldg(&g_adj[bs + lane]) : 0;
        int j = 0;
        for (; j + 3 < cnt; j += 4) {
            int p0 = __shfl_sync(0xFFFFFFFFu, p, j);
            int p1 = __shfl_sync(0xFFFFFFFFu, p, j + 1);
            int p2 = __shfl_sync(0xFFFFFFFFu, p, j + 2);
            int p3 = __shfl_sync(0xFFFFFFFFu, p, j + 3);
            int s0 = p0 & 0xFFFFFF, e0 = p0 >> 24;
            int s1 = p1 & 0xFFFFFF, e1 = p1 >> 24;
            int s2 = p2 & 0xFFFFFF, e2 = p2 >> 24;
            int s3 = p3 & 0xFFFFFF, e3 = p3 >> 24;
            float aj0 = __ldg(&g_aj[s0 * H + h]);
            float aj1 = __ldg(&g_aj[s1 * H + h]);
            float aj2 = __ldg(&g_aj[s2 * H + h]);
            float aj3 = __ldg(&g_aj[s3 * H + h]);
            uint2 h0 = __ldg(reinterpret_cast<const uint2*>(g_xvh + (size_t)s0 * D) + lane);
            uint2 h1 = __ldg(reinterpret_cast<const uint2*>(g_xvh + (size_t)s1 * D) + lane);
            uint2 h2 = __ldg(reinterpret_cast<const uint2*>(g_xvh + (size_t)s2 * D) + lane);
            uint2 h3 = __ldg(reinterpret_cast<const uint2*>(g_xvh + (size_t)s3 * D) + lane);
            float a0 = ai_h + aj0 + s_aje[e0 * H + h];
            float a1 = ai_h + aj1 + s_aje[e1 * H + h];
            float a2 = ai_h + aj2 + s_aje[e2 * H + h];
            float a3 = ai_h + aj3 + s_aje[e3 * H + h];
            a0 = fmaxf(a0, NEG_SLOPE * a0);
            a1 = fmaxf(a1, NEG_SLOPE * a1);
            a2 = fmaxf(a2, NEG_SLOPE * a2);
            a3 = fmaxf(a3, NEG_SLOPE * a3);
            float w0 = __expf(a0), w1 = __expf(a1);
            float w2 = __expf(a2), w3 = __expf(a3);
            denom += w0; denom += w1; denom += w2; denom += w3;
            if (my_et == e0) wsum += w0;
            if (my_et == e1) wsum += w1;
            if (my_et == e2) wsum += w2;
            if (my_et == e3) wsum += w3;
            float4 v0 = h4_to_f4(h0);
            float4 v1 = h4_to_f4(h1);
            float4 v2 = h4_to_f4(h2);
            float4 v3 = h4_to_f4(h3);
            acc.x = fmaf(w0, v0.x, acc.x);
            acc.y = fmaf(w0, v0.y, acc.y);
            acc.z = fmaf(w0, v0.z, acc.z);
            acc.w = fmaf(w0, v0.w, acc.w);
            acc.x = fmaf(w1, v1.x, acc.x);
            acc.y = fmaf(w1, v1.y, acc.y);
            acc.z = fmaf(w1, v1.z, acc.z);
            acc.w = fmaf(w1, v1.w, acc.w);
            acc.x = fmaf(w2, v2.x, acc.x);
            acc.y = fmaf(w2, v2.y, acc.y);
            acc.z = fmaf(w2, v2.z, acc.z);
            acc.w = fmaf(w2, v2.w, acc.w);
            acc.x = fmaf(w3, v3.x, acc.x);
            acc.y = fmaf(w3, v3.y, acc.y);
            acc.z = fmaf(w3, v3.z, acc.z);
            acc.w = fmaf(w3, v3.w, acc.w);
        }
        for (; j < cnt; j++) {
            int p0 = __shfl_sync(0xFFFFFFFFu, p, j);
            int s0 = p0 & 0xFFFFFF, e0 = p0 >> 24;
            float aj0 = __ldg(&g_aj[s0 * H + h]);
            uint2 h0 = __ldg(reinterpret_cast<const uint2*>(g_xvh + (size_t)s0 * D) + lane);
            float a0 = ai_h + aj0 + s_aje[e0 * H + h];
            a0 = fmaxf(a0, NEG_SLOPE * a0);
            float w0 = __expf(a0);
            denom += w0;
            if (my_et == e0) wsum += w0;
            float4 v0 = h4_to_f4(h0);
            acc.x = fmaf(w0, v0.x, acc.x);
            acc.y = fmaf(w0, v0.y, acc.y);
            acc.z = fmaf(w0, v0.z, acc.z);
            acc.w = fmaf(w0, v0.w, acc.w);
        }
    }

    // epilogue: apply edge-type embedding contributions
    #pragma unroll
    for (int et = 0; et < 8; et++) {
        float wet = __shfl_sync(0xFFFFFFFFu, wsum, (lane & 24) | et);
        const float4 ee = *reinterpret_cast<const float4*>(&s_xve[et * D + lane * 4]);
        acc.x = fmaf(wet, ee.x, acc.x);
        acc.y = fmaf(wet, ee.y, acc.y);
        acc.z = fmaf(wet, ee.z, acc.z);
        acc.w = fmaf(wet, ee.w, acc.w);
    }

    float inv = 1.f / (denom + 1e-16f);
    float4 b4 = __ldg(reinterpret_cast<const float4*>(bias) + lane);
    float4 r;
    r.x = fmaf(acc.x, inv, b4.x);
    r.y = fmaf(acc.y, inv, b4.y);
    r.z = fmaf(acc.z, inv, b4.z);
    r.w = fmaf(acc.w, inv, b4.w);
    reinterpret_cast<float4*>(out + (size_t)n * D)[lane] = r;
}

extern "C" void kernel_launch(void* const* d_in, const int* in_sizes, int n_in,
                              void* d_out, int out_size) {
    const float* x         = (const float*)d_in[0];
    const int*   ei        = (const int*)  d_in[1];
    const int*   node_type = (const int*)d_in[2];
    const int*   edge_type = (const int*)d_in[3];
    const float* Wq        = (const float*)d_in[4];
    const float* Wk        = (const float*)d_in[5];
    const float* Wv        = (const float*)d_in[6];
    const float* att_i     = (const float*)d_in[7];
    const float* att_j     = (const float*)d_in[8];
    const float* bias      = (const float*)d_in[9];
    const float* node_emb  = (const float*)d_in[10];
    const float* edge_emb  = (const float*)d_in[11];
    float* out = (float*)d_out;

    int N = in_sizes[2];
    int E = in_sizes[3];
    int nb = (N + SCAN_BLK - 1) / SCAN_BLK;
    int zblocks = (N + 127) / 128;

    cudaStream_t s2;
    cudaEvent_t evFork, evJoin;
    cudaStreamCreateWithFlags(&s2, cudaStreamNonBlocking);
    cudaEventCreateWithFlags(&evFork, cudaEventDisableTiming);
    cudaEventCreateWithFlags(&evJoin, cudaEventDisableTiming);

    // fused precompute + deg-zero on capture stream, before the fork
    precompute_kernel<<<140 + zblocks, 128>>>(Wq, Wk, Wv, att_i, att_j, edge_emb, N);

    // fork: branch B = node GEMM; branch A = CSR build
    cudaEventRecord(evFork, 0);
    cudaStreamWaitEvent(s2, evFork, 0);
    node_kernel<<<(N + MTILE - 1) / MTILE, 128, 0, s2>>>(x, node_type, node_emb, N);
    cudaEventRecord(evJoin, s2);

    hist_kernel<<<(E + 255) / 256, 256>>>(ei, E);
    scan1_kernel<<<nb, SCAN_BLK>>>(N);
    scan3_kernel<<<nb, SCAN_BLK>>>(N);
    scatter_kernel<<<(E + 255) / 256, 256>>>(ei, edge_type, E);

    cudaStreamWaitEvent(0, evJoin, 0);
    gather_kernel<<<(N * 32 + 255) / 256, 256>>>(out, bias, N);
}